// round 9
// baseline (speedup 1.0000x reference)
#include <cuda_runtime.h>
#include <math.h>

#define NMAX 100000
#define EMAX 3200000
#define NEG 0.2f

// ---------------- scratch (device globals; no allocations) ----------------
__device__ float4 g_xl1[NMAX * 4];   // [N,4,4] layer1 left proj
__device__ float4 g_xr1[NMAX * 4];   // [N,4,4] layer1 right proj
__device__ float4 g_acc1[NMAX * 4];  // softmax numerator accum
__device__ float4 g_den1[NMAX];      // softmax denominator, 4 heads packed
__device__ float4 g_xl2[NMAX * 8];   // [N,4,8]
__device__ float4 g_xr2[NMAX * 8];
__device__ float4 g_acc2[NMAX * 8];
__device__ float4 g_den2[NMAX];      // 4 heads packed
__device__ float4 g_lc[NMAX];        // {sum ew, sum ce, in-degree, pad} per dst
__device__ float2 g_ps[NMAX];        // h_final . W[2:34]
__device__ float2 g_pd[NMAX];        // h_final . W[34:66]
__device__ float  g_W[132];          // collapsed edge MLP weights [66,2]
__device__ float  g_Wb[2];           // collapsed bias
__device__ __align__(16) float g_Wp[128]; // packed {Ws0,Ws1,Wd0,Wd1} per k=0..31

// ---------------- weights (16B aligned for float4 loads) ----------------
__device__ __align__(16) float c_w_init[40];
__device__ __align__(16) float c_b_init[8];
__device__ __align__(16) float c_w1l[128], c_b1l[16], c_w1r[128], c_b1r[16];
__device__ __align__(16) float c_w1e[32], c_att1[16], c_bias1[16];
__device__ __align__(16) float c_w2l[512], c_b2l[32], c_w2r[512], c_b2r[32];
__device__ __align__(16) float c_w2e[64], c_att2[32], c_bias2[32];
__device__ __align__(16) float c_wfc[1024], c_bfc[32];

__device__ __forceinline__ float lrelu(float x) { return x > 0.f ? x : NEG * x; }
__device__ __forceinline__ float4 ldg4(const float* p) { return __ldg((const float4*)p); }
__device__ __forceinline__ void fma4(float4& a, float s, float4 w) {
    a.x += s * w.x; a.y += s * w.y; a.z += s * w.z; a.w += s * w.w;
}
__device__ __forceinline__ float4 lrelu4(float4 m) {
    return make_float4(lrelu(m.x), lrelu(m.y), lrelu(m.z), lrelu(m.w));
}
__device__ __forceinline__ float dot4(float4 a, float4 b) {
    return a.x * b.x + a.y * b.y + a.z * b.z + a.w * b.w;
}

__device__ __forceinline__ void redAdd4(float4* p, float4 v) {
    asm volatile("red.global.add.v4.f32 [%0], {%1,%2,%3,%4};"
                 :: "l"(p), "f"(v.x), "f"(v.y), "f"(v.z), "f"(v.w) : "memory");
}

// ---------------- weight setup: copy into device globals + collapse MLP ----
__global__ void k_weights(
    const float* w_init, const float* b_init,
    const float* w1l, const float* b1l, const float* w1r, const float* b1r,
    const float* w1e, const float* att1, const float* bias1,
    const float* w2l, const float* b2l, const float* w2r, const float* b2r,
    const float* w2e, const float* att2, const float* bias2,
    const float* wfc, const float* bfc,
    const float* we1, const float* be1, const float* we2, const float* be2)
{
    int i = threadIdx.x;  // 1024 threads
    if (i < 40)   c_w_init[i] = w_init[i];
    if (i < 8)    c_b_init[i] = b_init[i];
    if (i < 128)  { c_w1l[i] = w1l[i]; c_w1r[i] = w1r[i]; }
    if (i < 16)   { c_b1l[i] = b1l[i]; c_b1r[i] = b1r[i];
                    c_att1[i] = att1[i]; c_bias1[i] = bias1[i]; }
    if (i < 32)   { c_w1e[i] = w1e[i]; c_b2l[i] = b2l[i]; c_b2r[i] = b2r[i];
                    c_att2[i] = att2[i]; c_bias2[i] = bias2[i]; c_bfc[i] = bfc[i]; }
    if (i < 512)  { c_w2l[i] = w2l[i]; c_w2r[i] = w2r[i]; }
    if (i < 64)   c_w2e[i] = w2e[i];
    if (i < 1024) c_wfc[i] = wfc[i];

    // collapsed edge MLP: W = we1 @ we2 (66x2), Wb = be1 @ we2 + be2
    if (i < 66) {
        float a = 0.f, b = 0.f;
#pragma unroll
        for (int k = 0; k < 32; k++) {
            float w = we1[i * 32 + k];
            a += w * we2[k * 2 + 0];
            b += w * we2[k * 2 + 1];
        }
        g_W[i * 2 + 0] = a;
        g_W[i * 2 + 1] = b;
    } else if (i == 66) {
        float a = be2[0], b = be2[1];
        for (int k = 0; k < 32; k++) {
            a += be1[k] * we2[k * 2 + 0];
            b += be1[k] * we2[k * 2 + 1];
        }
        g_Wb[0] = a; g_Wb[1] = b;
    }
    __syncthreads();
    // packed ps/pd weights: g_Wp[k*4+{0..3}] = {W[2+k][0],W[2+k][1],W[34+k][0],W[34+k][1]}
    if (i < 32) {
        g_Wp[i * 4 + 0] = g_W[(2 + i) * 2 + 0];
        g_Wp[i * 4 + 1] = g_W[(2 + i) * 2 + 1];
        g_Wp[i * 4 + 2] = g_W[(34 + i) * 2 + 0];
        g_Wp[i * 4 + 3] = g_W[(34 + i) * 2 + 1];
    }
}

// ---------------- node: zero accumulators + init MLP + layer1 projections --
__global__ void __launch_bounds__(128, 6) k_nodes1(const float* __restrict__ x, int N) {
    int n = blockIdx.x * blockDim.x + threadIdx.x;
    if (n >= N) return;

    float4 z4 = make_float4(0.f, 0.f, 0.f, 0.f);
    g_lc[n] = z4;
    g_den1[n] = z4;
    g_den2[n] = z4;
#pragma unroll
    for (int q = 0; q < 4; q++) g_acc1[n * 4 + q] = z4;
#pragma unroll
    for (int q = 0; q < 8; q++) g_acc2[n * 8 + q] = z4;

    float xi[5];
#pragma unroll
    for (int i = 0; i < 5; i++) xi[i] = x[n * 5 + i];

    float4 a0 = ldg4(c_b_init), a1 = ldg4(c_b_init + 4);
#pragma unroll
    for (int i = 0; i < 5; i++) {
        fma4(a0, xi[i], ldg4(c_w_init + i * 8));
        fma4(a1, xi[i], ldg4(c_w_init + i * 8 + 4));
    }
    float h0[8] = {fmaxf(a0.x, 0.f), fmaxf(a0.y, 0.f), fmaxf(a0.z, 0.f), fmaxf(a0.w, 0.f),
                   fmaxf(a1.x, 0.f), fmaxf(a1.y, 0.f), fmaxf(a1.z, 0.f), fmaxf(a1.w, 0.f)};

    {
        float4 v[4];
#pragma unroll
        for (int q = 0; q < 4; q++) v[q] = ldg4(c_b1l + q * 4);
#pragma unroll
        for (int i = 0; i < 8; i++) {
            float s = h0[i];
#pragma unroll
            for (int q = 0; q < 4; q++) fma4(v[q], s, ldg4(c_w1l + i * 16 + q * 4));
        }
#pragma unroll
        for (int q = 0; q < 4; q++) g_xl1[n * 4 + q] = v[q];
    }
    {
        float4 v[4];
#pragma unroll
        for (int q = 0; q < 4; q++) v[q] = ldg4(c_b1r + q * 4);
#pragma unroll
        for (int i = 0; i < 8; i++) {
            float s = h0[i];
#pragma unroll
            for (int q = 0; q < 4; q++) fma4(v[q], s, ldg4(c_w1r + i * 16 + q * 4));
        }
#pragma unroll
        for (int q = 0; q < 4; q++) g_xr1[n * 4 + q] = v[q];
    }
}

// ---------------- edge pass, layer 1 (1 thread/edge, 4 heads) --------------
__global__ void k_edge1(const int* __restrict__ ei, const float* __restrict__ ew,
                        const float* __restrict__ ce, int E) {
    int e = blockIdx.x * blockDim.x + threadIdx.x;
    if (e >= E) return;
    int s = __ldg(ei + e);
    int d = __ldg(ei + (size_t)E + e);
    float w = __ldg(ew + e), c = __ldg(ce + e);

    redAdd4(&g_lc[d], make_float4(w, c, 1.f, 0.f));

    float ex[4];
#pragma unroll
    for (int h = 0; h < 4; h++) {
        float4 xl = g_xl1[s * 4 + h];
        float4 xr = g_xr1[d * 4 + h];
        float4 wa = ldg4(&c_w1e[h * 4]);
        float4 wb = ldg4(&c_w1e[16 + h * 4]);
        float4 at = ldg4(&c_att1[h * 4]);
        float4 m;
        m.x = xl.x + xr.x + w * wa.x + c * wb.x;
        m.y = xl.y + xr.y + w * wa.y + c * wb.y;
        m.z = xl.z + xr.z + w * wa.z + c * wb.z;
        m.w = xl.w + xr.w + w * wa.w + c * wb.w;
        ex[h] = __expf(dot4(lrelu4(m), at));
        redAdd4(&g_acc1[d * 4 + h],
                make_float4(ex[h] * xl.x, ex[h] * xl.y, ex[h] * xl.z, ex[h] * xl.w));
    }
    redAdd4(&g_den1[d], make_float4(ex[0], ex[1], ex[2], ex[3]));
}

// ---------------- node: self-loop + normalize layer1 + layer2 projections --
__global__ void __launch_bounds__(128, 6) k_selfnorm1(int N) {
    int n = blockIdx.x * blockDim.x + threadIdx.x;
    if (n >= N) return;
    float4 lc = g_lc[n];
    float icnt = __fdividef(1.f, fmaxf(lc.z, 1.f));
    float la0 = lc.x * icnt, la1 = lc.y * icnt;
    float4 den4 = g_den1[n];
    float dv[4] = {den4.x, den4.y, den4.z, den4.w};
    float h1[16];
#pragma unroll
    for (int h = 0; h < 4; h++) {
        float4 xl = g_xl1[n * 4 + h];
        float4 xr = g_xr1[n * 4 + h];
        float4 wa = ldg4(&c_w1e[h * 4]);
        float4 wb = ldg4(&c_w1e[16 + h * 4]);
        float4 at = ldg4(&c_att1[h * 4]);
        float4 m;
        m.x = xl.x + xr.x + la0 * wa.x + la1 * wb.x;
        m.y = xl.y + xr.y + la0 * wa.y + la1 * wb.y;
        m.z = xl.z + xr.z + la0 * wa.z + la1 * wb.z;
        m.w = xl.w + xr.w + la0 * wa.w + la1 * wb.w;
        float ex = __expf(dot4(lrelu4(m), at));
        float iden = __fdividef(1.f, dv[h] + ex);
        float4 ac = g_acc1[n * 4 + h];
        float4 bi = ldg4(&c_bias1[h * 4]);
        h1[h * 4 + 0] = fmaxf((ac.x + ex * xl.x) * iden + bi.x, 0.f);
        h1[h * 4 + 1] = fmaxf((ac.y + ex * xl.y) * iden + bi.y, 0.f);
        h1[h * 4 + 2] = fmaxf((ac.z + ex * xl.z) * iden + bi.z, 0.f);
        h1[h * 4 + 3] = fmaxf((ac.w + ex * xl.w) * iden + bi.w, 0.f);
    }
    {
        float4 v[8];
#pragma unroll
        for (int q = 0; q < 8; q++) v[q] = ldg4(c_b2l + q * 4);
#pragma unroll
        for (int i = 0; i < 16; i++) {
            float s = h1[i];
#pragma unroll
            for (int q = 0; q < 8; q++) fma4(v[q], s, ldg4(c_w2l + i * 32 + q * 4));
        }
#pragma unroll
        for (int q = 0; q < 8; q++) g_xl2[n * 8 + q] = v[q];
    }
    {
        float4 v[8];
#pragma unroll
        for (int q = 0; q < 8; q++) v[q] = ldg4(c_b2r + q * 4);
#pragma unroll
        for (int i = 0; i < 16; i++) {
            float s = h1[i];
#pragma unroll
            for (int q = 0; q < 8; q++) fma4(v[q], s, ldg4(c_w2r + i * 32 + q * 4));
        }
#pragma unroll
        for (int q = 0; q < 8; q++) g_xr2[n * 8 + q] = v[q];
    }
}

// ---------------- edge pass, layer 2 (1 thread/edge, 4 heads) --------------
__global__ void k_edge2(const int* __restrict__ ei, const float* __restrict__ ew,
                        const float* __restrict__ ce, int E) {
    int e = blockIdx.x * blockDim.x + threadIdx.x;
    if (e >= E) return;
    int s = __ldg(ei + e);
    int d = __ldg(ei + (size_t)E + e);
    float w = __ldg(ew + e), c = __ldg(ce + e);

    float ex[4];
#pragma unroll
    for (int h = 0; h < 4; h++) {
        float4 a0 = g_xl2[s * 8 + h * 2], a1 = g_xl2[s * 8 + h * 2 + 1];
        float4 b0 = g_xr2[d * 8 + h * 2], b1 = g_xr2[d * 8 + h * 2 + 1];
        float4 wa0 = ldg4(&c_w2e[h * 8]),      wa1 = ldg4(&c_w2e[h * 8 + 4]);
        float4 wb0 = ldg4(&c_w2e[32 + h * 8]), wb1 = ldg4(&c_w2e[32 + h * 8 + 4]);
        float4 at0 = ldg4(&c_att2[h * 8]),     at1 = ldg4(&c_att2[h * 8 + 4]);
        float4 m0, m1;
        m0.x = a0.x + b0.x + w * wa0.x + c * wb0.x;
        m0.y = a0.y + b0.y + w * wa0.y + c * wb0.y;
        m0.z = a0.z + b0.z + w * wa0.z + c * wb0.z;
        m0.w = a0.w + b0.w + w * wa0.w + c * wb0.w;
        m1.x = a1.x + b1.x + w * wa1.x + c * wb1.x;
        m1.y = a1.y + b1.y + w * wa1.y + c * wb1.y;
        m1.z = a1.z + b1.z + w * wa1.z + c * wb1.z;
        m1.w = a1.w + b1.w + w * wa1.w + c * wb1.w;
        float al = dot4(lrelu4(m0), at0) + dot4(lrelu4(m1), at1);
        float exh = __expf(al);
        ex[h] = exh;
        redAdd4(&g_acc2[d * 8 + h * 2],
                make_float4(exh * a0.x, exh * a0.y, exh * a0.z, exh * a0.w));
        redAdd4(&g_acc2[d * 8 + h * 2 + 1],
                make_float4(exh * a1.x, exh * a1.y, exh * a1.z, exh * a1.w));
    }
    redAdd4(&g_den2[d], make_float4(ex[0], ex[1], ex[2], ex[3]));
}

// ---------------- node: self-loop + normalize layer2 + FC + ps/pd ----------
__global__ void __launch_bounds__(128, 6) k_selfnorm2(int N) {
    int n = blockIdx.x * blockDim.x + threadIdx.x;
    if (n >= N) return;
    float4 lc = g_lc[n];
    float icnt = __fdividef(1.f, fmaxf(lc.z, 1.f));
    float la0 = lc.x * icnt, la1 = lc.y * icnt;
    float4 den4 = g_den2[n];
    float dv[4] = {den4.x, den4.y, den4.z, den4.w};
    float h2[32];
#pragma unroll
    for (int h = 0; h < 4; h++) {
        float4 a0 = g_xl2[n * 8 + h * 2], a1 = g_xl2[n * 8 + h * 2 + 1];
        float4 b0 = g_xr2[n * 8 + h * 2], b1 = g_xr2[n * 8 + h * 2 + 1];
        float4 wa0 = ldg4(&c_w2e[h * 8]),      wa1 = ldg4(&c_w2e[h * 8 + 4]);
        float4 wb0 = ldg4(&c_w2e[32 + h * 8]), wb1 = ldg4(&c_w2e[32 + h * 8 + 4]);
        float4 at0 = ldg4(&c_att2[h * 8]),     at1 = ldg4(&c_att2[h * 8 + 4]);
        float4 m0, m1;
        m0.x = a0.x + b0.x + la0 * wa0.x + la1 * wb0.x;
        m0.y = a0.y + b0.y + la0 * wa0.y + la1 * wb0.y;
        m0.z = a0.z + b0.z + la0 * wa0.z + la1 * wb0.z;
        m0.w = a0.w + b0.w + la0 * wa0.w + la1 * wb0.w;
        m1.x = a1.x + b1.x + la0 * wa1.x + la1 * wb1.x;
        m1.y = a1.y + b1.y + la0 * wa1.y + la1 * wb1.y;
        m1.z = a1.z + b1.z + la0 * wa1.z + la1 * wb1.z;
        m1.w = a1.w + b1.w + la0 * wa1.w + la1 * wb1.w;
        float ex = __expf(dot4(lrelu4(m0), at0) + dot4(lrelu4(m1), at1));
        float iden = __fdividef(1.f, dv[h] + ex);
        float4 c0 = g_acc2[n * 8 + h * 2], c1 = g_acc2[n * 8 + h * 2 + 1];
        float4 bi0 = ldg4(&c_bias2[h * 8]), bi1 = ldg4(&c_bias2[h * 8 + 4]);
        h2[h * 8 + 0] = fmaxf((c0.x + ex * a0.x) * iden + bi0.x, 0.f);
        h2[h * 8 + 1] = fmaxf((c0.y + ex * a0.y) * iden + bi0.y, 0.f);
        h2[h * 8 + 2] = fmaxf((c0.z + ex * a0.z) * iden + bi0.z, 0.f);
        h2[h * 8 + 3] = fmaxf((c0.w + ex * a0.w) * iden + bi0.w, 0.f);
        h2[h * 8 + 4] = fmaxf((c1.x + ex * a1.x) * iden + bi1.x, 0.f);
        h2[h * 8 + 5] = fmaxf((c1.y + ex * a1.y) * iden + bi1.y, 0.f);
        h2[h * 8 + 6] = fmaxf((c1.z + ex * a1.z) * iden + bi1.z, 0.f);
        h2[h * 8 + 7] = fmaxf((c1.w + ex * a1.w) * iden + bi1.w, 0.f);
    }
    float p0 = 0.f, p1 = 0.f, q0 = 0.f, q1 = 0.f;
#pragma unroll
    for (int half = 0; half < 2; half++) {
        float4 acc[4];
#pragma unroll
        for (int q = 0; q < 4; q++) acc[q] = ldg4(c_bfc + half * 16 + q * 4);
#pragma unroll
        for (int i = 0; i < 32; i++) {
            float v = h2[i];
#pragma unroll
            for (int q = 0; q < 4; q++)
                fma4(acc[q], v, ldg4(c_wfc + i * 32 + half * 16 + q * 4));
        }
#pragma unroll
        for (int q = 0; q < 4; q++) {
            float hv[4] = {fmaxf(acc[q].x, 0.f), fmaxf(acc[q].y, 0.f),
                           fmaxf(acc[q].z, 0.f), fmaxf(acc[q].w, 0.f)};
#pragma unroll
            for (int cmp = 0; cmp < 4; cmp++) {
                int k = half * 16 + q * 4 + cmp;
                float4 wp = ldg4(&g_Wp[k * 4]);
                p0 += hv[cmp] * wp.x; p1 += hv[cmp] * wp.y;
                q0 += hv[cmp] * wp.z; q1 += hv[cmp] * wp.w;
            }
        }
    }
    g_ps[n] = make_float2(p0, p1);
    g_pd[n] = make_float2(q0, q1);
}

// ---------------- final edge output ----------------
__global__ void k_edgeout(const int* __restrict__ ei, const float* __restrict__ ew,
                          const float* __restrict__ ce, float* __restrict__ out, int E) {
    int e = blockIdx.x * blockDim.x + threadIdx.x;
    if (e >= E) return;
    int s = __ldg(ei + e);
    int d = __ldg(ei + (size_t)E + e);
    float w = __ldg(ew + e), c = __ldg(ce + e);
    float2 ps = g_ps[s];
    float2 pd = g_pd[d];
    float2 o;
    o.x = __ldg(&g_Wb[0]) + w * __ldg(&g_W[0]) + c * __ldg(&g_W[2]) + ps.x + pd.x;
    o.y = __ldg(&g_Wb[1]) + w * __ldg(&g_W[1]) + c * __ldg(&g_W[3]) + ps.y + pd.y;
    ((float2*)out)[e] = o;
}

// ---------------- launch ----------------
extern "C" void kernel_launch(void* const* d_in, const int* in_sizes, int n_in,
                              void* d_out, int out_size) {
    const float* x  = (const float*)d_in[0];
    const int*   ei = (const int*)d_in[1];   // int32 [2,E]
    const float* ew = (const float*)d_in[2];
    const float* ce = (const float*)d_in[3];
    int N = in_sizes[0] / 5;
    int E = in_sizes[2];

    k_weights<<<1, 1024>>>(
        (const float*)d_in[4],  (const float*)d_in[5],
        (const float*)d_in[6],  (const float*)d_in[7],
        (const float*)d_in[8],  (const float*)d_in[9],
        (const float*)d_in[10], (const float*)d_in[11], (const float*)d_in[12],
        (const float*)d_in[13], (const float*)d_in[14],
        (const float*)d_in[15], (const float*)d_in[16],
        (const float*)d_in[17], (const float*)d_in[18], (const float*)d_in[19],
        (const float*)d_in[20], (const float*)d_in[21],
        (const float*)d_in[22], (const float*)d_in[23],
        (const float*)d_in[24], (const float*)d_in[25]);

    int nb = (N + 127) / 128;
    k_nodes1<<<nb, 128>>>(x, N);

    int eb = (E + 255) / 256;
    k_edge1<<<eb, 256>>>(ei, ew, ce, E);
    k_selfnorm1<<<nb, 128>>>(N);
    k_edge2<<<eb, 256>>>(ei, ew, ce, E);
    k_selfnorm2<<<nb, 128>>>(N);
    k_edgeout<<<eb, 256>>>(ei, ew, ce, (float*)d_out, E);
}

// round 10
// speedup vs baseline: 1.6750x; 1.6750x over previous
#include <cuda_runtime.h>
#include <math.h>

#define NMAX 100000
#define EMAX 3200000
#define NEG 0.2f

// ---------------- scratch (device globals; no allocations) ----------------
__device__ float4 g_xl1[NMAX * 4];   // [N,4,4] layer1 left proj
__device__ float4 g_xr1[NMAX * 4];   // [N,4,4] layer1 right proj
__device__ float4 g_acc1[NMAX * 4];  // softmax numerator accum
__device__ float  g_den1[NMAX * 4];  // softmax denominator accum
__device__ float4 g_xl2[NMAX * 8];   // [N,4,8]
__device__ float4 g_xr2[NMAX * 8];
__device__ float4 g_acc2[NMAX * 8];
__device__ float  g_den2[NMAX * 4];
__device__ float4 g_lc[NMAX];        // {sum ew, sum ce, in-degree, pad} per dst
__device__ float2 g_ps[NMAX];        // h_final . W[2:34]
__device__ float2 g_pd[NMAX];        // h_final . W[34:66]
__device__ float  g_W[132];          // collapsed edge MLP weights [66,2]
__device__ float  g_Wb[2];           // collapsed bias
__device__ __align__(16) float g_Wp[128]; // packed {Ws0,Ws1,Wd0,Wd1} per k=0..31

// ---------------- weights (16B aligned for float4 loads) ----------------
__device__ __align__(16) float c_w_init[40];
__device__ __align__(16) float c_b_init[8];
__device__ __align__(16) float c_w1l[128], c_b1l[16], c_w1r[128], c_b1r[16];
__device__ __align__(16) float c_w1e[32], c_att1[16], c_bias1[16];
__device__ __align__(16) float c_w2l[512], c_b2l[32], c_w2r[512], c_b2r[32];
__device__ __align__(16) float c_w2e[64], c_att2[32], c_bias2[32];
__device__ __align__(16) float c_wfc[1024], c_bfc[32];

__device__ __forceinline__ float lrelu(float x) { return x > 0.f ? x : NEG * x; }
__device__ __forceinline__ float4 ldg4(const float* p) { return __ldg((const float4*)p); }
__device__ __forceinline__ void fma4(float4& a, float s, float4 w) {
    a.x += s * w.x; a.y += s * w.y; a.z += s * w.z; a.w += s * w.w;
}
__device__ __forceinline__ float4 lrelu4(float4 m) {
    return make_float4(lrelu(m.x), lrelu(m.y), lrelu(m.z), lrelu(m.w));
}
__device__ __forceinline__ float dot4(float4 a, float4 b) {
    return a.x * b.x + a.y * b.y + a.z * b.z + a.w * b.w;
}

__device__ __forceinline__ void redAdd(float* p, float v) {
    asm volatile("red.global.add.f32 [%0], %1;" :: "l"(p), "f"(v) : "memory");
}
__device__ __forceinline__ void redAdd4(float4* p, float4 v) {
    asm volatile("red.global.add.v4.f32 [%0], {%1,%2,%3,%4};"
                 :: "l"(p), "f"(v.x), "f"(v.y), "f"(v.z), "f"(v.w) : "memory");
}

// ---------------- weight setup: copy into device globals + collapse MLP ----
__global__ void k_weights(
    const float* w_init, const float* b_init,
    const float* w1l, const float* b1l, const float* w1r, const float* b1r,
    const float* w1e, const float* att1, const float* bias1,
    const float* w2l, const float* b2l, const float* w2r, const float* b2r,
    const float* w2e, const float* att2, const float* bias2,
    const float* wfc, const float* bfc,
    const float* we1, const float* be1, const float* we2, const float* be2)
{
    int i = threadIdx.x;  // 1024 threads
    if (i < 40)   c_w_init[i] = w_init[i];
    if (i < 8)    c_b_init[i] = b_init[i];
    if (i < 128)  { c_w1l[i] = w1l[i]; c_w1r[i] = w1r[i]; }
    if (i < 16)   { c_b1l[i] = b1l[i]; c_b1r[i] = b1r[i];
                    c_att1[i] = att1[i]; c_bias1[i] = bias1[i]; }
    if (i < 32)   { c_w1e[i] = w1e[i]; c_b2l[i] = b2l[i]; c_b2r[i] = b2r[i];
                    c_att2[i] = att2[i]; c_bias2[i] = bias2[i]; c_bfc[i] = bfc[i]; }
    if (i < 512)  { c_w2l[i] = w2l[i]; c_w2r[i] = w2r[i]; }
    if (i < 64)   c_w2e[i] = w2e[i];
    if (i < 1024) c_wfc[i] = wfc[i];

    // collapsed edge MLP: W = we1 @ we2 (66x2), Wb = be1 @ we2 + be2
    if (i < 66) {
        float a = 0.f, b = 0.f;
#pragma unroll
        for (int k = 0; k < 32; k++) {
            float w = we1[i * 32 + k];
            a += w * we2[k * 2 + 0];
            b += w * we2[k * 2 + 1];
        }
        g_W[i * 2 + 0] = a;
        g_W[i * 2 + 1] = b;
    } else if (i == 66) {
        float a = be2[0], b = be2[1];
        for (int k = 0; k < 32; k++) {
            a += be1[k] * we2[k * 2 + 0];
            b += be1[k] * we2[k * 2 + 1];
        }
        g_Wb[0] = a; g_Wb[1] = b;
    }
    __syncthreads();
    // packed ps/pd weights: g_Wp[k*4+{0..3}] = {W[2+k][0],W[2+k][1],W[34+k][0],W[34+k][1]}
    if (i < 32) {
        g_Wp[i * 4 + 0] = g_W[(2 + i) * 2 + 0];
        g_Wp[i * 4 + 1] = g_W[(2 + i) * 2 + 1];
        g_Wp[i * 4 + 2] = g_W[(34 + i) * 2 + 0];
        g_Wp[i * 4 + 3] = g_W[(34 + i) * 2 + 1];
    }
}

// ---------------- node: zero accumulators + init MLP + layer1 projections --
__global__ void __launch_bounds__(128, 6) k_nodes1(const float* __restrict__ x, int N) {
    int n = blockIdx.x * blockDim.x + threadIdx.x;
    if (n >= N) return;

    float4 z4 = make_float4(0.f, 0.f, 0.f, 0.f);
    g_lc[n] = z4;
#pragma unroll
    for (int q = 0; q < 4; q++) {
        g_den1[n * 4 + q] = 0.f;
        g_den2[n * 4 + q] = 0.f;
        g_acc1[n * 4 + q] = z4;
    }
#pragma unroll
    for (int q = 0; q < 8; q++) g_acc2[n * 8 + q] = z4;

    float xi[5];
#pragma unroll
    for (int i = 0; i < 5; i++) xi[i] = x[n * 5 + i];

    float4 a0 = ldg4(c_b_init), a1 = ldg4(c_b_init + 4);
#pragma unroll
    for (int i = 0; i < 5; i++) {
        fma4(a0, xi[i], ldg4(c_w_init + i * 8));
        fma4(a1, xi[i], ldg4(c_w_init + i * 8 + 4));
    }
    float h0[8] = {fmaxf(a0.x, 0.f), fmaxf(a0.y, 0.f), fmaxf(a0.z, 0.f), fmaxf(a0.w, 0.f),
                   fmaxf(a1.x, 0.f), fmaxf(a1.y, 0.f), fmaxf(a1.z, 0.f), fmaxf(a1.w, 0.f)};

    // left projection, then right (register reuse)
    {
        float4 v[4];
#pragma unroll
        for (int q = 0; q < 4; q++) v[q] = ldg4(c_b1l + q * 4);
#pragma unroll
        for (int i = 0; i < 8; i++) {
            float s = h0[i];
#pragma unroll
            for (int q = 0; q < 4; q++) fma4(v[q], s, ldg4(c_w1l + i * 16 + q * 4));
        }
#pragma unroll
        for (int q = 0; q < 4; q++) g_xl1[n * 4 + q] = v[q];
    }
    {
        float4 v[4];
#pragma unroll
        for (int q = 0; q < 4; q++) v[q] = ldg4(c_b1r + q * 4);
#pragma unroll
        for (int i = 0; i < 8; i++) {
            float s = h0[i];
#pragma unroll
            for (int q = 0; q < 4; q++) fma4(v[q], s, ldg4(c_w1r + i * 16 + q * 4));
        }
#pragma unroll
        for (int q = 0; q < 4; q++) g_xr1[n * 4 + q] = v[q];
    }
}

// ---------------- edge pass, layer 1 (4 threads/edge = one head each) ------
__global__ void k_edge1(const int* __restrict__ ei, const float* __restrict__ ew,
                        const float* __restrict__ ce, int E) {
    int t = blockIdx.x * blockDim.x + threadIdx.x;
    int e = t >> 2, h = t & 3;
    if (e >= E) return;
    int s = __ldg(ei + e);
    int d = __ldg(ei + (size_t)E + e);
    float w = __ldg(ew + e), c = __ldg(ce + e);
    if (h == 0) {
        redAdd4(&g_lc[d], make_float4(w, c, 1.f, 0.f));
    }
    float4 xl = g_xl1[s * 4 + h];
    float4 xr = g_xr1[d * 4 + h];
    float4 wa = ldg4(&c_w1e[h * 4]);
    float4 wb = ldg4(&c_w1e[16 + h * 4]);
    float4 at = ldg4(&c_att1[h * 4]);
    float4 m;
    m.x = xl.x + xr.x + w * wa.x + c * wb.x;
    m.y = xl.y + xr.y + w * wa.y + c * wb.y;
    m.z = xl.z + xr.z + w * wa.z + c * wb.z;
    m.w = xl.w + xr.w + w * wa.w + c * wb.w;
    float al = dot4(lrelu4(m), at);
    float ex = __expf(al);
    redAdd(&g_den1[d * 4 + h], ex);
    redAdd4(&g_acc1[d * 4 + h], make_float4(ex * xl.x, ex * xl.y, ex * xl.z, ex * xl.w));
}

// ---------------- node: self-loop + normalize layer1 + layer2 projections --
__global__ void __launch_bounds__(128, 6) k_selfnorm1(int N) {
    int n = blockIdx.x * blockDim.x + threadIdx.x;
    if (n >= N) return;
    float4 lc = g_lc[n];
    float icnt = __fdividef(1.f, fmaxf(lc.z, 1.f));
    float la0 = lc.x * icnt, la1 = lc.y * icnt;
    float h1[16];
#pragma unroll
    for (int h = 0; h < 4; h++) {
        float4 xl = g_xl1[n * 4 + h];
        float4 xr = g_xr1[n * 4 + h];
        float4 wa = ldg4(&c_w1e[h * 4]);
        float4 wb = ldg4(&c_w1e[16 + h * 4]);
        float4 at = ldg4(&c_att1[h * 4]);
        float4 m;
        m.x = xl.x + xr.x + la0 * wa.x + la1 * wb.x;
        m.y = xl.y + xr.y + la0 * wa.y + la1 * wb.y;
        m.z = xl.z + xr.z + la0 * wa.z + la1 * wb.z;
        m.w = xl.w + xr.w + la0 * wa.w + la1 * wb.w;
        float ex = __expf(dot4(lrelu4(m), at));
        float iden = __fdividef(1.f, g_den1[n * 4 + h] + ex);
        float4 ac = g_acc1[n * 4 + h];
        float4 bi = ldg4(&c_bias1[h * 4]);
        h1[h * 4 + 0] = fmaxf((ac.x + ex * xl.x) * iden + bi.x, 0.f);
        h1[h * 4 + 1] = fmaxf((ac.y + ex * xl.y) * iden + bi.y, 0.f);
        h1[h * 4 + 2] = fmaxf((ac.z + ex * xl.z) * iden + bi.z, 0.f);
        h1[h * 4 + 3] = fmaxf((ac.w + ex * xl.w) * iden + bi.w, 0.f);
    }
    // left projection then right projection (register reuse halves pressure)
    {
        float4 v[8];
#pragma unroll
        for (int q = 0; q < 8; q++) v[q] = ldg4(c_b2l + q * 4);
#pragma unroll
        for (int i = 0; i < 16; i++) {
            float s = h1[i];
#pragma unroll
            for (int q = 0; q < 8; q++) fma4(v[q], s, ldg4(c_w2l + i * 32 + q * 4));
        }
#pragma unroll
        for (int q = 0; q < 8; q++) g_xl2[n * 8 + q] = v[q];
    }
    {
        float4 v[8];
#pragma unroll
        for (int q = 0; q < 8; q++) v[q] = ldg4(c_b2r + q * 4);
#pragma unroll
        for (int i = 0; i < 16; i++) {
            float s = h1[i];
#pragma unroll
            for (int q = 0; q < 8; q++) fma4(v[q], s, ldg4(c_w2r + i * 32 + q * 4));
        }
#pragma unroll
        for (int q = 0; q < 8; q++) g_xr2[n * 8 + q] = v[q];
    }
}

// ---------------- edge pass, layer 2 ----------------
__global__ void k_edge2(const int* __restrict__ ei, const float* __restrict__ ew,
                        const float* __restrict__ ce, int E) {
    int t = blockIdx.x * blockDim.x + threadIdx.x;
    int e = t >> 2, h = t & 3;
    if (e >= E) return;
    int s = __ldg(ei + e);
    int d = __ldg(ei + (size_t)E + e);
    float w = __ldg(ew + e), c = __ldg(ce + e);
    float4 a0 = g_xl2[s * 8 + h * 2], a1 = g_xl2[s * 8 + h * 2 + 1];
    float4 b0 = g_xr2[d * 8 + h * 2], b1 = g_xr2[d * 8 + h * 2 + 1];
    float4 wa0 = ldg4(&c_w2e[h * 8]),      wa1 = ldg4(&c_w2e[h * 8 + 4]);
    float4 wb0 = ldg4(&c_w2e[32 + h * 8]), wb1 = ldg4(&c_w2e[32 + h * 8 + 4]);
    float4 at0 = ldg4(&c_att2[h * 8]),     at1 = ldg4(&c_att2[h * 8 + 4]);
    float4 m0, m1;
    m0.x = a0.x + b0.x + w * wa0.x + c * wb0.x;
    m0.y = a0.y + b0.y + w * wa0.y + c * wb0.y;
    m0.z = a0.z + b0.z + w * wa0.z + c * wb0.z;
    m0.w = a0.w + b0.w + w * wa0.w + c * wb0.w;
    m1.x = a1.x + b1.x + w * wa1.x + c * wb1.x;
    m1.y = a1.y + b1.y + w * wa1.y + c * wb1.y;
    m1.z = a1.z + b1.z + w * wa1.z + c * wb1.z;
    m1.w = a1.w + b1.w + w * wa1.w + c * wb1.w;
    float al = dot4(lrelu4(m0), at0) + dot4(lrelu4(m1), at1);
    float ex = __expf(al);
    redAdd(&g_den2[d * 4 + h], ex);
    redAdd4(&g_acc2[d * 8 + h * 2],
            make_float4(ex * a0.x, ex * a0.y, ex * a0.z, ex * a0.w));
    redAdd4(&g_acc2[d * 8 + h * 2 + 1],
            make_float4(ex * a1.x, ex * a1.y, ex * a1.z, ex * a1.w));
}

// ---------------- node: self-loop + normalize layer2 + FC + ps/pd ----------
__global__ void __launch_bounds__(128, 6) k_selfnorm2(int N) {
    int n = blockIdx.x * blockDim.x + threadIdx.x;
    if (n >= N) return;
    float4 lc = g_lc[n];
    float icnt = __fdividef(1.f, fmaxf(lc.z, 1.f));
    float la0 = lc.x * icnt, la1 = lc.y * icnt;
    float h2[32];
#pragma unroll
    for (int h = 0; h < 4; h++) {
        float4 a0 = g_xl2[n * 8 + h * 2], a1 = g_xl2[n * 8 + h * 2 + 1];
        float4 b0 = g_xr2[n * 8 + h * 2], b1 = g_xr2[n * 8 + h * 2 + 1];
        float4 wa0 = ldg4(&c_w2e[h * 8]),      wa1 = ldg4(&c_w2e[h * 8 + 4]);
        float4 wb0 = ldg4(&c_w2e[32 + h * 8]), wb1 = ldg4(&c_w2e[32 + h * 8 + 4]);
        float4 at0 = ldg4(&c_att2[h * 8]),     at1 = ldg4(&c_att2[h * 8 + 4]);
        float4 m0, m1;
        m0.x = a0.x + b0.x + la0 * wa0.x + la1 * wb0.x;
        m0.y = a0.y + b0.y + la0 * wa0.y + la1 * wb0.y;
        m0.z = a0.z + b0.z + la0 * wa0.z + la1 * wb0.z;
        m0.w = a0.w + b0.w + la0 * wa0.w + la1 * wb0.w;
        m1.x = a1.x + b1.x + la0 * wa1.x + la1 * wb1.x;
        m1.y = a1.y + b1.y + la0 * wa1.y + la1 * wb1.y;
        m1.z = a1.z + b1.z + la0 * wa1.z + la1 * wb1.z;
        m1.w = a1.w + b1.w + la0 * wa1.w + la1 * wb1.w;
        float ex = __expf(dot4(lrelu4(m0), at0) + dot4(lrelu4(m1), at1));
        float iden = __fdividef(1.f, g_den2[n * 4 + h] + ex);
        float4 c0 = g_acc2[n * 8 + h * 2], c1 = g_acc2[n * 8 + h * 2 + 1];
        float4 bi0 = ldg4(&c_bias2[h * 8]), bi1 = ldg4(&c_bias2[h * 8 + 4]);
        h2[h * 8 + 0] = fmaxf((c0.x + ex * a0.x) * iden + bi0.x, 0.f);
        h2[h * 8 + 1] = fmaxf((c0.y + ex * a0.y) * iden + bi0.y, 0.f);
        h2[h * 8 + 2] = fmaxf((c0.z + ex * a0.z) * iden + bi0.z, 0.f);
        h2[h * 8 + 3] = fmaxf((c0.w + ex * a0.w) * iden + bi0.w, 0.f);
        h2[h * 8 + 4] = fmaxf((c1.x + ex * a1.x) * iden + bi1.x, 0.f);
        h2[h * 8 + 5] = fmaxf((c1.y + ex * a1.y) * iden + bi1.y, 0.f);
        h2[h * 8 + 6] = fmaxf((c1.z + ex * a1.z) * iden + bi1.z, 0.f);
        h2[h * 8 + 7] = fmaxf((c1.w + ex * a1.w) * iden + bi1.w, 0.f);
    }
    // FC 32->32 in two 16-column halves; fold ps/pd dot products incrementally
    float p0 = 0.f, p1 = 0.f, q0 = 0.f, q1 = 0.f;
#pragma unroll
    for (int half = 0; half < 2; half++) {
        float4 acc[4];
#pragma unroll
        for (int q = 0; q < 4; q++) acc[q] = ldg4(c_bfc + half * 16 + q * 4);
#pragma unroll
        for (int i = 0; i < 32; i++) {
            float v = h2[i];
#pragma unroll
            for (int q = 0; q < 4; q++)
                fma4(acc[q], v, ldg4(c_wfc + i * 32 + half * 16 + q * 4));
        }
#pragma unroll
        for (int q = 0; q < 4; q++) {
            float hv[4] = {fmaxf(acc[q].x, 0.f), fmaxf(acc[q].y, 0.f),
                           fmaxf(acc[q].z, 0.f), fmaxf(acc[q].w, 0.f)};
#pragma unroll
            for (int cmp = 0; cmp < 4; cmp++) {
                int k = half * 16 + q * 4 + cmp;
                float4 wp = ldg4(&g_Wp[k * 4]);
                p0 += hv[cmp] * wp.x; p1 += hv[cmp] * wp.y;
                q0 += hv[cmp] * wp.z; q1 += hv[cmp] * wp.w;
            }
        }
    }
    g_ps[n] = make_float2(p0, p1);
    g_pd[n] = make_float2(q0, q1);
}

// ---------------- final edge output ----------------
__global__ void k_edgeout(const int* __restrict__ ei, const float* __restrict__ ew,
                          const float* __restrict__ ce, float* __restrict__ out, int E) {
    int e = blockIdx.x * blockDim.x + threadIdx.x;
    if (e >= E) return;
    int s = __ldg(ei + e);
    int d = __ldg(ei + (size_t)E + e);
    float w = __ldg(ew + e), c = __ldg(ce + e);
    float2 ps = g_ps[s];
    float2 pd = g_pd[d];
    float2 o;
    o.x = __ldg(&g_Wb[0]) + w * __ldg(&g_W[0]) + c * __ldg(&g_W[2]) + ps.x + pd.x;
    o.y = __ldg(&g_Wb[1]) + w * __ldg(&g_W[1]) + c * __ldg(&g_W[3]) + ps.y + pd.y;
    ((float2*)out)[e] = o;
}

// ---------------- launch ----------------
extern "C" void kernel_launch(void* const* d_in, const int* in_sizes, int n_in,
                              void* d_out, int out_size) {
    const float* x  = (const float*)d_in[0];
    const int*   ei = (const int*)d_in[1];   // int32 [2,E]
    const float* ew = (const float*)d_in[2];
    const float* ce = (const float*)d_in[3];
    int N = in_sizes[0] / 5;
    int E = in_sizes[2];

    k_weights<<<1, 1024>>>(
        (const float*)d_in[4],  (const float*)d_in[5],
        (const float*)d_in[6],  (const float*)d_in[7],
        (const float*)d_in[8],  (const float*)d_in[9],
        (const float*)d_in[10], (const float*)d_in[11], (const float*)d_in[12],
        (const float*)d_in[13], (const float*)d_in[14],
        (const float*)d_in[15], (const float*)d_in[16],
        (const float*)d_in[17], (const float*)d_in[18], (const float*)d_in[19],
        (const float*)d_in[20], (const float*)d_in[21],
        (const float*)d_in[22], (const float*)d_in[23],
        (const float*)d_in[24], (const float*)d_in[25]);

    int nb = (N + 127) / 128;
    k_nodes1<<<nb, 128>>>(x, N);

    long long tE = 4LL * E;
    int eb = (int)((tE + 255) / 256);
    k_edge1<<<eb, 256>>>(ei, ew, ce, E);
    k_selfnorm1<<<nb, 128>>>(N);
    k_edge2<<<eb, 256>>>(ei, ew, ce, E);
    k_selfnorm2<<<nb, 128>>>(N);
    k_edgeout<<<(E + 255) / 256, 256>>>(ei, ew, ce, (float*)d_out, E);
}